// round 2
// baseline (speedup 1.0000x reference)
#include <cuda_runtime.h>
#include <cuda_fp16.h>

// Problem constants (from reference): B=16, S=512, V=8192, D=512
#define V_DIM 8192
#define D_DIM 512
#define NROWS 8192          // B*S
#define CAP   4096          // nonzero-list capacity per row (expected nnz ~82)
#define NG    4             // nonzero groups of 64 threads each
#define THREADS 256

// 8 MB scratch for W^T in fp16 (static __device__ array: no runtime alloc)
__device__ __half g_Wt[(size_t)V_DIM * D_DIM];

// ---------------------------------------------------------------------------
// Kernel 1: W [D, V] fp32  ->  Wt [V, D] fp16   (tiled transpose via smem)
// ---------------------------------------------------------------------------
__global__ void transpose_convert_kernel(const float* __restrict__ W) {
    __shared__ float tile[32][33];
    const int v0 = blockIdx.x * 32;
    const int d0 = blockIdx.y * 32;
    const int tx = threadIdx.x;          // 0..31
    const int ty = threadIdx.y;          // 0..7

    #pragma unroll
    for (int r = ty; r < 32; r += 8) {
        tile[r][tx] = W[(size_t)(d0 + r) * V_DIM + v0 + tx];
    }
    __syncthreads();
    #pragma unroll
    for (int r = ty; r < 32; r += 8) {
        g_Wt[(size_t)(v0 + r) * D_DIM + d0 + tx] = __float2half(tile[tx][r]);
    }
}

// ---------------------------------------------------------------------------
// Kernel 2: one CTA per output row m in [0, B*S)
//   Phase 1a: each thread counts nonzeros in its strided slice of x[m,:]
//   Phase 1b: block exclusive scan of counts (deterministic list order)
//   Phase 1c: second pass (L1 hits) writes (idx, val) at scanned offsets
//   Phase 2 : NG groups x 64 threads gather fp16 Wt rows, fp32 accumulate
//   Phase 3 : reduce groups in smem, tanh, store
// ---------------------------------------------------------------------------
__global__ __launch_bounds__(THREADS) void sparse_row_kernel(
    const float* __restrict__ x,
    float* __restrict__ out)
{
    __shared__ float val_s[CAP];              // 16 KB
    __shared__ int   idx_s[CAP];              // 16 KB
    __shared__ float red_s[NG * D_DIM];       //  8 KB
    __shared__ int   scan_s[THREADS + 1];

    const int m = blockIdx.x;
    const int t = threadIdx.x;

    const float4* xrow = reinterpret_cast<const float4*>(x + (size_t)m * V_DIM);
    constexpr int KITER = V_DIM / 4 / THREADS;            // 8

    // ---- Phase 1a: count ----
    int cnt = 0;
    #pragma unroll
    for (int k = 0; k < KITER; k++) {
        const float4 f = xrow[t + k * THREADS];
        cnt += (f.x != 0.0f) + (f.y != 0.0f) + (f.z != 0.0f) + (f.w != 0.0f);
    }
    scan_s[t + 1] = cnt;
    if (t == 0) scan_s[0] = 0;
    __syncthreads();

    // ---- Phase 1b: Hillis-Steele inclusive scan over scan_s[1..THREADS] ----
    #pragma unroll
    for (int off = 1; off < THREADS; off <<= 1) {
        int v = scan_s[t + 1];
        int w = (t + 1 > off) ? scan_s[t + 1 - off] : 0;
        __syncthreads();
        scan_s[t + 1] = v + w;
        __syncthreads();
    }
    const int total = scan_s[THREADS];
    int pos = scan_s[t];                                   // exclusive offset

    // ---- Phase 1c: write (deterministic order; x row is L1-hot) ----
    #pragma unroll
    for (int k = 0; k < KITER; k++) {
        const int   vec = t + k * THREADS;
        const float4 f  = xrow[vec];
        const int vbase = vec * 4;
        if (f.x != 0.0f && pos < CAP) { idx_s[pos] = vbase + 0; val_s[pos] = f.x; pos++; }
        if (f.y != 0.0f && pos < CAP) { idx_s[pos] = vbase + 1; val_s[pos] = f.y; pos++; }
        if (f.z != 0.0f && pos < CAP) { idx_s[pos] = vbase + 2; val_s[pos] = f.z; pos++; }
        if (f.w != 0.0f && pos < CAP) { idx_s[pos] = vbase + 3; val_s[pos] = f.w; pos++; }
    }
    __syncthreads();
    const int n = (total < CAP) ? total : CAP;

    // ---- Phase 2: gather Wt rows, fp32 accumulate ----
    const int g = t >> 6;       // nonzero group 0..3
    const int s = t & 63;       // d-slice: dims [s*8, s*8+8)

    float acc[8];
    #pragma unroll
    for (int j = 0; j < 8; j++) acc[j] = 0.0f;

    for (int i = g; i < n; i += NG) {
        const int   v  = idx_s[i];
        const float xv = val_s[i];
        // 16 bytes = 8 halves of Wt[v]; per warp: 512B contiguous (4 sectors/row)
        const uint4 w = *(reinterpret_cast<const uint4*>(g_Wt + (size_t)v * D_DIM) + s);
        const __half2* h = reinterpret_cast<const __half2*>(&w);
        #pragma unroll
        for (int q = 0; q < 4; q++) {
            const float2 f = __half22float2(h[q]);
            acc[2 * q + 0] += xv * f.x;
            acc[2 * q + 1] += xv * f.y;
        }
    }

    // ---- Phase 3: reduce across groups, tanh, store ----
    #pragma unroll
    for (int j = 0; j < 8; j++) red_s[g * D_DIM + s * 8 + j] = acc[j];
    __syncthreads();

    float2* orow = reinterpret_cast<float2*>(out + (size_t)m * D_DIM);
    const int d0 = t * 2;
    float s0 = red_s[d0]     + red_s[D_DIM + d0]     + red_s[2 * D_DIM + d0]     + red_s[3 * D_DIM + d0];
    float s1 = red_s[d0 + 1] + red_s[D_DIM + d0 + 1] + red_s[2 * D_DIM + d0 + 1] + red_s[3 * D_DIM + d0 + 1];
    float2 o;
    o.x = tanhf(s0);
    o.y = tanhf(s1);
    orow[t] = o;
}

// ---------------------------------------------------------------------------
extern "C" void kernel_launch(void* const* d_in, const int* in_sizes, int n_in,
                              void* d_out, int out_size) {
    const float* x = (const float*)d_in[0];   // [16, 512, 8192] fp32
    const float* W = (const float*)d_in[1];   // [512, 8192]    fp32
    float* out = (float*)d_out;               // [16, 512, 512] fp32

    (void)in_sizes; (void)n_in; (void)out_size;

    dim3 tgrid(V_DIM / 32, D_DIM / 32);       // (256, 16)
    dim3 tblk(32, 8);
    transpose_convert_kernel<<<tgrid, tblk>>>(W);

    sparse_row_kernel<<<NROWS, THREADS>>>(x, out);
}

// round 4
// speedup vs baseline: 1.2499x; 1.2499x over previous
#include <cuda_runtime.h>
#include <cuda_fp16.h>

// Problem constants: B=16, S=512, V=8192, D=512
#define V_DIM 8192
#define D_DIM 512
#define NROWS 8192          // B*S
#define NWARP 8             // warps per CTA
#define CAPW  128           // per-warp nonzero capacity (expected ~10)
#define CAP   (NWARP*CAPW)  // 1024 total
#define NG    4             // gather groups of 64 threads
#define THREADS 256

// 8 MB scratch for W^T in fp16 (static __device__ array: no runtime alloc)
__device__ __half g_Wt[(size_t)V_DIM * D_DIM];

// ---------------------------------------------------------------------------
// Kernel 1: W [D, V] fp32 -> Wt [V, D] fp16  (tiled transpose via smem)
// ---------------------------------------------------------------------------
__global__ void transpose_convert_kernel(const float* __restrict__ W) {
    __shared__ float tile[32][33];
    const int v0 = blockIdx.x * 32;
    const int d0 = blockIdx.y * 32;
    const int tx = threadIdx.x;          // 0..31
    const int ty = threadIdx.y;          // 0..7

    #pragma unroll
    for (int r = ty; r < 32; r += 8)
        tile[r][tx] = W[(size_t)(d0 + r) * V_DIM + v0 + tx];
    __syncthreads();
    #pragma unroll
    for (int r = ty; r < 32; r += 8)
        g_Wt[(size_t)(v0 + r) * D_DIM + d0 + tx] = __float2half(tile[tx][r]);
}

// ---------------------------------------------------------------------------
// Kernel 2: one CTA per output row m
//   Phase 1 : single pass; each warp ballot-compacts its 1024-elem x slice
//             into a per-warp smem segment (deterministic order, no atomics)
//   Phase 1.5: warps copy segments into one contiguous list
//   Phase 2 : NG groups x 64 threads gather fp16 Wt rows (__ldcg, L2-only),
//             fp32 accumulate 8 dims/thread, unrolled x2 for MLP
//   Phase 3 : reduce groups in smem, tanh, store
// ---------------------------------------------------------------------------
__global__ __launch_bounds__(THREADS) void sparse_row_kernel(
    const float* __restrict__ x,
    float* __restrict__ out)
{
    __shared__ int   seg_idx[NWARP][CAPW];    // 4 KB
    __shared__ float seg_val[NWARP][CAPW];    // 4 KB
    __shared__ int   idx_s[CAP];              // 4 KB
    __shared__ float val_s[CAP];              // 4 KB
    __shared__ float red_s[NG * D_DIM];       // 8 KB
    __shared__ int   cnt_s[NWARP];

    const int m    = blockIdx.x;
    const int t    = threadIdx.x;
    const int w    = t >> 5;
    const int lane = t & 31;

    // ---- Phase 1: ballot compaction, one pass over x ----
    const float4* xw = reinterpret_cast<const float4*>(
        x + (size_t)m * V_DIM + w * (V_DIM / NWARP));
    int base = 0;
    #pragma unroll
    for (int j = 0; j < V_DIM / NWARP / 4 / 32; j++) {          // 8 iters
        const float4 f = __ldcs(&xw[lane + 32 * j]);
        const int vbase = w * (V_DIM / NWARP) + (lane + 32 * j) * 4;
        const float vv[4] = {f.x, f.y, f.z, f.w};
        #pragma unroll
        for (int c = 0; c < 4; c++) {
            const bool nz = (vv[c] != 0.0f);
            const unsigned msk = __ballot_sync(0xffffffffu, nz);
            if (nz) {
                const int p = base + __popc(msk & ((1u << lane) - 1u));
                if (p < CAPW) { seg_idx[w][p] = vbase + c; seg_val[w][p] = vv[c]; }
            }
            base += __popc(msk);
        }
    }
    if (lane == 0) cnt_s[w] = (base < CAPW) ? base : CAPW;
    __syncthreads();

    // ---- Phase 1.5: concatenate segments (deterministic order) ----
    int cnts[NWARP];
    #pragma unroll
    for (int q = 0; q < NWARP; q++) cnts[q] = cnt_s[q];
    int start = 0, total = 0;
    #pragma unroll
    for (int q = 0; q < NWARP; q++) {
        if (q < w) start += cnts[q];
        total += cnts[q];
    }
    const int cw = cnts[w];
    for (int i = lane; i < cw; i += 32) {
        idx_s[start + i] = seg_idx[w][i];
        val_s[start + i] = seg_val[w][i];
    }
    __syncthreads();
    const int n = total;

    // ---- Phase 2: gather Wt rows via L2 (__ldcg), fp32 accumulate ----
    const int g = t >> 6;       // group 0..3
    const int s = t & 63;       // d-slice: dims [s*8, s*8+8)

    float acc[8];
    #pragma unroll
    for (int j = 0; j < 8; j++) acc[j] = 0.0f;

    int i = g;
    for (; i + NG < n; i += 2 * NG) {
        const int   v0 = idx_s[i];
        const float a0 = val_s[i];
        const int   v1 = idx_s[i + NG];
        const float a1 = val_s[i + NG];
        const uint4 w0 = __ldcg(reinterpret_cast<const uint4*>(g_Wt + (size_t)v0 * D_DIM) + s);
        const uint4 w1 = __ldcg(reinterpret_cast<const uint4*>(g_Wt + (size_t)v1 * D_DIM) + s);
        const __half2* h0 = reinterpret_cast<const __half2*>(&w0);
        const __half2* h1 = reinterpret_cast<const __half2*>(&w1);
        #pragma unroll
        for (int q = 0; q < 4; q++) {
            const float2 f0 = __half22float2(h0[q]);
            const float2 f1 = __half22float2(h1[q]);
            acc[2 * q + 0] += a0 * f0.x + a1 * f1.x;
            acc[2 * q + 1] += a0 * f0.y + a1 * f1.y;
        }
    }
    for (; i < n; i += NG) {
        const int   v  = idx_s[i];
        const float xv = val_s[i];
        const uint4 wv = __ldcg(reinterpret_cast<const uint4*>(g_Wt + (size_t)v * D_DIM) + s);
        const __half2* h = reinterpret_cast<const __half2*>(&wv);
        #pragma unroll
        for (int q = 0; q < 4; q++) {
            const float2 f = __half22float2(h[q]);
            acc[2 * q + 0] += xv * f.x;
            acc[2 * q + 1] += xv * f.y;
        }
    }

    // ---- Phase 3: reduce across groups, tanh, store ----
    #pragma unroll
    for (int j = 0; j < 8; j++) red_s[g * D_DIM + s * 8 + j] = acc[j];
    __syncthreads();

    float2* orow = reinterpret_cast<float2*>(out + (size_t)m * D_DIM);
    const int d0 = t * 2;
    const float s0 = red_s[d0]     + red_s[D_DIM + d0]     + red_s[2 * D_DIM + d0]     + red_s[3 * D_DIM + d0];
    const float s1 = red_s[d0 + 1] + red_s[D_DIM + d0 + 1] + red_s[2 * D_DIM + d0 + 1] + red_s[3 * D_DIM + d0 + 1];
    float2 o;
    o.x = tanhf(s0);
    o.y = tanhf(s1);
    orow[t] = o;
}

// ---------------------------------------------------------------------------
extern "C" void kernel_launch(void* const* d_in, const int* in_sizes, int n_in,
                              void* d_out, int out_size) {
    const float* x = (const float*)d_in[0];   // [16, 512, 8192] fp32
    const float* W = (const float*)d_in[1];   // [512, 8192]    fp32
    float* out = (float*)d_out;               // [16, 512, 512] fp32

    (void)in_sizes; (void)n_in; (void)out_size;

    dim3 tgrid(V_DIM / 32, D_DIM / 32);       // (256, 16)
    dim3 tblk(32, 8);
    transpose_convert_kernel<<<tgrid, tblk>>>(W);

    sparse_row_kernel<<<NROWS, THREADS>>>(x, out);
}